// round 1
// baseline (speedup 1.0000x reference)
#include <cuda_runtime.h>
#include <math.h>

#define N_NODES 100000
#define N_EDGES 1600000
#define F_IN    128
#define F_E     32
#define DH      128   // D*H
#define NH      4     // heads

// -------- scratch (static device globals; no allocation allowed) --------
__device__ float g_node_proj[(size_t)N_NODES * DH];   // 51.2 MB
__device__ float g_ssrc[N_NODES * NH];
__device__ float g_sdst[N_NODES * NH];
__device__ float g_p[(size_t)N_EDGES * NH];           // 25.6 MB
__device__ float g_denom[N_NODES * NH];               // later holds 1/(denom+eps)
__device__ float g_agg[(size_t)N_NODES * DH];         // 51.2 MB
__device__ float g_v[NH * F_E];                       // folded W_edge @ a_edge

// -------- v[h][k] = sum_d W_edge[k, h*32+d] * a_edge[h][d] --------
__global__ void k_prep_v(const float* __restrict__ W_edge,
                         const float* __restrict__ AK) {
    int t = threadIdx.x;            // 128 threads
    int h = t >> 5, k = t & 31;
    float s = 0.f;
#pragma unroll
    for (int d = 0; d < 32; d++)
        s += W_edge[k * DH + h * 32 + d] * AK[h * 96 + 64 + d];
    g_v[h * 32 + k] = s;
}

// -------- zero agg + denom --------
__global__ void k_zero() {
    const size_t agg4 = (size_t)N_NODES * DH / 4;
    const size_t den4 = (size_t)N_NODES * NH / 4;
    const size_t tot = agg4 + den4;
    float4 z = make_float4(0.f, 0.f, 0.f, 0.f);
    for (size_t i = (size_t)blockIdx.x * blockDim.x + threadIdx.x; i < tot;
         i += (size_t)gridDim.x * blockDim.x) {
        if (i < agg4) reinterpret_cast<float4*>(g_agg)[i] = z;
        else          reinterpret_cast<float4*>(g_denom)[i - agg4] = z;
    }
}

// -------- node_proj = node_features @ W_node  (64x128 tile per block) --------
__global__ void __launch_bounds__(256) k_node_gemm(const float* __restrict__ NF,
                                                   const float* __restrict__ W) {
    __shared__ float As[64 * 129];
    int t = threadIdx.x;
    int row0 = blockIdx.x * 64;
    // cooperative load of 64x128 A tile (padded rows, conflict-free)
#pragma unroll
    for (int i = 0; i < 32; i++) {
        int idx = i * 256 + t;
        int r = idx >> 7, k = idx & 127;
        int gr = row0 + r;
        As[r * 129 + k] = (gr < N_NODES) ? NF[(size_t)gr * F_IN + k] : 0.f;
    }
    __syncthreads();

    int tx = t & 31, ty = t >> 5;   // tx: col group (4 cols), ty: row group (8 rows)
    float acc[8][4];
#pragma unroll
    for (int i = 0; i < 8; i++)
#pragma unroll
        for (int j = 0; j < 4; j++) acc[i][j] = 0.f;

    const float4* W4 = reinterpret_cast<const float4*>(W);
#pragma unroll 4
    for (int k = 0; k < 128; k++) {
        float4 b = W4[k * 32 + tx];           // coalesced, L1-resident (64KB)
#pragma unroll
        for (int i = 0; i < 8; i++) {
            float a = As[(ty * 8 + i) * 129 + k];   // broadcast
            acc[i][0] += a * b.x;
            acc[i][1] += a * b.y;
            acc[i][2] += a * b.z;
            acc[i][3] += a * b.w;
        }
    }
#pragma unroll
    for (int i = 0; i < 8; i++) {
        int gr = row0 + ty * 8 + i;
        if (gr < N_NODES) {
            float4 o = make_float4(acc[i][0], acc[i][1], acc[i][2], acc[i][3]);
            reinterpret_cast<float4*>(g_node_proj + (size_t)gr * DH)[tx] = o;
        }
    }
}

// -------- s_src[n,h], s_dst[n,h] from node_proj (1 warp per node) --------
__global__ void __launch_bounds__(256) k_scores(const float* __restrict__ AK) {
    int t = threadIdx.x;
    int lane = t & 31, w = t >> 5;
    int n = blockIdx.x * 8 + w;
    if (n >= N_NODES) return;
    float4 p = reinterpret_cast<const float4*>(g_node_proj + (size_t)n * DH)[lane];
    int h = lane >> 3;
    int dl = (lane & 7) * 4;
    const float* a = AK + h * 96;
    float ps = p.x * a[dl] + p.y * a[dl + 1] + p.z * a[dl + 2] + p.w * a[dl + 3];
    float pd = p.x * a[32 + dl] + p.y * a[32 + dl + 1] + p.z * a[32 + dl + 2] + p.w * a[32 + dl + 3];
#pragma unroll
    for (int o = 4; o >= 1; o >>= 1) {
        ps += __shfl_down_sync(0xffffffffu, ps, o, 8);
        pd += __shfl_down_sync(0xffffffffu, pd, o, 8);
    }
    if ((lane & 7) == 0) {
        g_ssrc[n * 4 + h] = ps;
        g_sdst[n * 4 + h] = pd;
    }
}

// -------- pass A: p = exp(logit); denom[dst] += p  (128 edges/block) --------
__global__ void __launch_bounds__(128) k_edgeA(const int* __restrict__ EI,
                                               const float* __restrict__ EF) {
    __shared__ float sef[128 * 36];   // 128 edges x 32 feats, padded stride 36
    __shared__ float sv[128];
    int t = threadIdx.x;
    int e0 = blockIdx.x * 128;
    sv[t] = g_v[t];
#pragma unroll
    for (int i = 0; i < 8; i++) {
        int j4 = i * 128 + t;
        int el = j4 >> 3, c4 = j4 & 7;
        float4 v = reinterpret_cast<const float4*>(EF + (size_t)(e0 + el) * F_E)[c4];
        *reinterpret_cast<float4*>(&sef[el * 36 + c4 * 4]) = v;
    }
    __syncthreads();

    int e = e0 + t;
    int2 ei = reinterpret_cast<const int2*>(EI)[e];
    float se0 = 0.f, se1 = 0.f, se2 = 0.f, se3 = 0.f;
#pragma unroll
    for (int j = 0; j < 32; j++) {
        float f = sef[t * 36 + j];
        se0 += f * sv[j];
        se1 += f * sv[32 + j];
        se2 += f * sv[64 + j];
        se3 += f * sv[96 + j];
    }
    float4 ss = reinterpret_cast<const float4*>(g_ssrc)[ei.x];
    float4 sd = reinterpret_cast<const float4*>(g_sdst)[ei.y];
    float4 p;
    p.x = __expf(ss.x + sd.x + se0);
    p.y = __expf(ss.y + sd.y + se1);
    p.z = __expf(ss.z + sd.z + se2);
    p.w = __expf(ss.w + sd.w + se3);
    reinterpret_cast<float4*>(g_p)[e] = p;
    atomicAdd(&g_denom[ei.y * 4 + 0], p.x);
    atomicAdd(&g_denom[ei.y * 4 + 1], p.y);
    atomicAdd(&g_denom[ei.y * 4 + 2], p.z);
    atomicAdd(&g_denom[ei.y * 4 + 3], p.w);
}

// -------- denom -> 1/(denom + 1e-8) --------
__global__ void k_inv() {
    int i = blockIdx.x * blockDim.x + threadIdx.x;
    if (i < N_NODES * NH) g_denom[i] = 1.f / (g_denom[i] + 1e-8f);
}

// -------- pass B: agg[dst] += attn * node_proj[src]  (1 warp per edge) --------
__global__ void __launch_bounds__(256) k_edgeB(const int* __restrict__ EI) {
    int t = threadIdx.x;
    int lane = t & 31, w = t >> 5;
    size_t e = (size_t)blockIdx.x * 8 + w;
    int2 ei = reinterpret_cast<const int2*>(EI)[e];
    int h = lane >> 3;
    float attn = g_p[e * 4 + h] * g_denom[ei.y * 4 + h];
    float4 np = reinterpret_cast<const float4*>(g_node_proj + (size_t)ei.x * DH)[lane];
    float4 m = make_float4(np.x * attn, np.y * attn, np.z * attn, np.w * attn);
    float* dst = g_agg + (size_t)ei.y * DH + lane * 4;
    asm volatile("red.global.add.v4.f32 [%0], {%1,%2,%3,%4};"
                 :: "l"(dst), "f"(m.x), "f"(m.y), "f"(m.z), "f"(m.w)
                 : "memory");
}

// -------- out = gelu(agg @ W_out + b)  (8 rows per block) --------
__global__ void __launch_bounds__(256) k_out(const float* __restrict__ Wo,
                                             const float* __restrict__ bo,
                                             float* __restrict__ out) {
    __shared__ float sW[128 * 32];
    __shared__ float sb[32];
    __shared__ float sA[8 * 128];
    int t = threadIdx.x;
    int n0 = blockIdx.x * 8;
#pragma unroll
    for (int i = 0; i < 16; i++) sW[i * 256 + t] = Wo[i * 256 + t];
    if (t < 32) sb[t] = bo[t];
#pragma unroll
    for (int i = 0; i < 4; i++) {
        int idx = i * 256 + t;
        int r = idx >> 7, k = idx & 127;
        int n = n0 + r;
        sA[idx] = (n < N_NODES) ? g_agg[(size_t)n * DH + k] : 0.f;
    }
    __syncthreads();
    int r = t >> 5, col = t & 31;
    float acc = 0.f;
#pragma unroll 8
    for (int k = 0; k < 128; k++) acc += sA[r * 128 + k] * sW[k * 32 + col];
    int n = n0 + r;
    if (n < N_NODES) {
        float v = acc + sb[col];
        out[(size_t)n * 32 + col] = 0.5f * v * (1.f + erff(v * 0.70710678118f));
    }
}

extern "C" void kernel_launch(void* const* d_in, const int* in_sizes, int n_in,
                              void* d_out, int out_size) {
    const float* NF = (const float*)d_in[0];   // node_features (N,128)
    const int*   EI = (const int*)  d_in[1];   // edge_index (E,2)
    const float* EF = (const float*)d_in[2];   // edge_features (E,32)
    const float* Wn = (const float*)d_in[3];   // W_node (128,128)
    const float* We = (const float*)d_in[4];   // W_edge (32,128)
    const float* AK = (const float*)d_in[5];   // attn_kernel (4,96)
    const float* Wo = (const float*)d_in[6];   // W_out (128,32)
    const float* bo = (const float*)d_in[7];   // b_out (32,)
    float* out = (float*)d_out;                // (N,32)

    k_prep_v<<<1, 128>>>(We, AK);
    k_zero<<<2048, 256>>>();
    k_node_gemm<<<(N_NODES + 63) / 64, 256>>>(NF, Wn);
    k_scores<<<(N_NODES + 7) / 8, 256>>>(AK);
    k_edgeA<<<N_EDGES / 128, 128>>>(EI, EF);
    k_inv<<<(N_NODES * NH + 255) / 256, 256>>>();
    k_edgeB<<<N_EDGES / 8, 256>>>(EI);
    k_out<<<(N_NODES + 7) / 8, 256>>>(Wo, bo, out);
}

// round 2
// speedup vs baseline: 1.2821x; 1.2821x over previous
#include <cuda_runtime.h>
#include <cuda_fp16.h>
#include <math.h>

#define N_NODES 100000
#define N_EDGES 1600000
#define F_IN    128
#define F_E     32
#define DH      128   // D*H
#define NH      4     // heads

// -------- scratch (static device globals; no allocation allowed) --------
__device__ __half2 g_np_h[(size_t)N_NODES * 64];      // node_proj fp16, 25.6 MB
__device__ float g_ssrc[N_NODES * NH];
__device__ float g_sdst[N_NODES * NH];
__device__ float g_denom[N_NODES * NH];               // unnormalized softmax denom
__device__ float g_agg[(size_t)N_NODES * DH];         // unnormalized aggregation
__device__ float g_v[NH * F_E];                       // folded W_edge @ a_edge

// -------- v[h][k] = sum_d W_edge[k, h*32+d] * a_edge[h][d] --------
__global__ void k_prep_v(const float* __restrict__ W_edge,
                         const float* __restrict__ AK) {
    int t = threadIdx.x;            // 128 threads
    int h = t >> 5, k = t & 31;
    float s = 0.f;
#pragma unroll
    for (int d = 0; d < 32; d++)
        s += W_edge[k * DH + h * 32 + d] * AK[h * 96 + 64 + d];
    g_v[h * 32 + k] = s;
}

// -------- zero agg + denom --------
__global__ void k_zero() {
    const size_t agg4 = (size_t)N_NODES * DH / 4;
    const size_t den4 = (size_t)N_NODES * NH / 4;
    const size_t tot = agg4 + den4;
    float4 z = make_float4(0.f, 0.f, 0.f, 0.f);
    for (size_t i = (size_t)blockIdx.x * blockDim.x + threadIdx.x; i < tot;
         i += (size_t)gridDim.x * blockDim.x) {
        if (i < agg4) reinterpret_cast<float4*>(g_agg)[i] = z;
        else          reinterpret_cast<float4*>(g_denom)[i - agg4] = z;
    }
}

// -------- node_proj = NF @ W_node (fp16 out) + fused s_src/s_dst scores --------
__global__ void __launch_bounds__(256) k_node_gemm(const float* __restrict__ NF,
                                                   const float* __restrict__ W,
                                                   const float* __restrict__ AK) {
    __shared__ float As[64 * 129];
    int t = threadIdx.x;
    int row0 = blockIdx.x * 64;
#pragma unroll
    for (int i = 0; i < 32; i++) {
        int idx = i * 256 + t;
        int r = idx >> 7, k = idx & 127;
        int gr = row0 + r;
        As[r * 129 + k] = (gr < N_NODES) ? NF[(size_t)gr * F_IN + k] : 0.f;
    }
    __syncthreads();

    int tx = t & 31, ty = t >> 5;   // tx: col group (4 cols), ty: row group (8 rows)
    float acc[8][4];
#pragma unroll
    for (int i = 0; i < 8; i++)
#pragma unroll
        for (int j = 0; j < 4; j++) acc[i][j] = 0.f;

    const float4* W4 = reinterpret_cast<const float4*>(W);
#pragma unroll 4
    for (int k = 0; k < 128; k++) {
        float4 b = W4[k * 32 + tx];           // coalesced, L1-resident (64KB)
#pragma unroll
        for (int i = 0; i < 8; i++) {
            float a = As[(ty * 8 + i) * 129 + k];   // broadcast
            acc[i][0] += a * b.x;
            acc[i][1] += a * b.y;
            acc[i][2] += a * b.z;
            acc[i][3] += a * b.w;
        }
    }

    // epilogue: fp16 store of node_proj + fused score dots
    int h = tx >> 3;                 // head owned by this lane's columns
    int dl = (tx & 7) * 4;           // d offset within head
    const float* a_s = AK + h * 96;
    const float* a_d = a_s + 32;
#pragma unroll
    for (int i = 0; i < 8; i++) {
        int gr = row0 + ty * 8 + i;
        if (gr < N_NODES) {
            __half2 h01 = __floats2half2_rn(acc[i][0], acc[i][1]);
            __half2 h23 = __floats2half2_rn(acc[i][2], acc[i][3]);
            uint2 raw;
            raw.x = *reinterpret_cast<unsigned*>(&h01);
            raw.y = *reinterpret_cast<unsigned*>(&h23);
            reinterpret_cast<uint2*>(g_np_h)[(size_t)gr * 32 + tx] = raw;
        }
        float ps = acc[i][0] * a_s[dl] + acc[i][1] * a_s[dl + 1]
                 + acc[i][2] * a_s[dl + 2] + acc[i][3] * a_s[dl + 3];
        float pd = acc[i][0] * a_d[dl] + acc[i][1] * a_d[dl + 1]
                 + acc[i][2] * a_d[dl + 2] + acc[i][3] * a_d[dl + 3];
#pragma unroll
        for (int o = 4; o >= 1; o >>= 1) {
            ps += __shfl_down_sync(0xffffffffu, ps, o, 8);
            pd += __shfl_down_sync(0xffffffffu, pd, o, 8);
        }
        int gr2 = row0 + ty * 8 + i;
        if ((tx & 7) == 0 && gr2 < N_NODES) {
            g_ssrc[gr2 * 4 + h] = ps;
            g_sdst[gr2 * 4 + h] = pd;
        }
    }
}

// -------- single fused edge pass: p=exp(logit); denom[dst]+=p; agg[dst]+=p*np[src]
__global__ void __launch_bounds__(256) k_edge(const int* __restrict__ EI,
                                              const float* __restrict__ EF) {
    __shared__ float sef[64 * 36];    // 64 edges x 32 feats, padded stride 36
    __shared__ float sv[128];
    __shared__ int2  sEI[64];
    __shared__ float sp[256];         // unnormalized attention p per (edge,head)
    int t = threadIdx.x;
    int e0 = blockIdx.x * 64;
    if (t < 128) sv[t] = g_v[t];
    if (t < 64)  sEI[t] = reinterpret_cast<const int2*>(EI)[e0 + t];
#pragma unroll
    for (int i = 0; i < 2; i++) {
        int idx = i * 256 + t;
        int el = idx >> 3, c4 = idx & 7;
        float4 v = reinterpret_cast<const float4*>(EF + (size_t)(e0 + el) * F_E)[c4];
        *reinterpret_cast<float4*>(&sef[el * 36 + c4 * 4]) = v;
    }
    __syncthreads();

    // phase 1: logits -> p, denom atomics. thread = (edge, head)
    {
        int el = t >> 2, h = t & 3;
        int2 ei = sEI[el];
        const float* vh = sv + h * 32;
        float se = 0.f;
#pragma unroll
        for (int j = 0; j < 32; j++) se += sef[el * 36 + j] * vh[j];
        float p = __expf(g_ssrc[ei.x * 4 + h] + g_sdst[ei.y * 4 + h] + se);
        sp[t] = p;
        atomicAdd(&g_denom[ei.y * 4 + h], p);
    }
    __syncthreads();

    // phase 2: 1 warp per 8 edges -> gather fp16 np row, scatter fp32 red
    int lane = t & 31, w = t >> 5;
    int hh = lane >> 3;
#pragma unroll
    for (int q = 0; q < 8; q++) {
        int e = w * 8 + q;
        int2 ei = sEI[e];
        float attn = sp[e * 4 + hh];
        uint2 raw = reinterpret_cast<const uint2*>(g_np_h)[(size_t)ei.x * 32 + lane];
        __half2 h01 = *reinterpret_cast<__half2*>(&raw.x);
        __half2 h23 = *reinterpret_cast<__half2*>(&raw.y);
        float2 f01 = __half22float2(h01);
        float2 f23 = __half22float2(h23);
        float* dst = g_agg + (size_t)ei.y * DH + lane * 4;
        asm volatile("red.global.add.v4.f32 [%0], {%1,%2,%3,%4};"
                     :: "l"(dst),
                        "f"(f01.x * attn), "f"(f01.y * attn),
                        "f"(f23.x * attn), "f"(f23.y * attn)
                     : "memory");
    }
}

// -------- out = gelu((agg/denom) @ W_out + b)  (8 rows per block) --------
__global__ void __launch_bounds__(256) k_out(const float* __restrict__ Wo,
                                             const float* __restrict__ bo,
                                             float* __restrict__ out) {
    __shared__ float sW[128 * 32];
    __shared__ float sb[32];
    __shared__ float sA[8 * 128];
    __shared__ float sdi[32];
    int t = threadIdx.x;
    int n0 = blockIdx.x * 8;
#pragma unroll
    for (int i = 0; i < 16; i++) sW[i * 256 + t] = Wo[i * 256 + t];
    if (t < 32) sb[t] = bo[t];
    if (t < 32) {
        int r = t >> 2, hh = t & 3;
        int n = n0 + r;
        sdi[t] = (n < N_NODES) ? 1.f / (g_denom[n * 4 + hh] + 1e-8f) : 0.f;
    }
    __syncthreads();
#pragma unroll
    for (int i = 0; i < 4; i++) {
        int idx = i * 256 + t;
        int r = idx >> 7, k = idx & 127;
        int n = n0 + r;
        sA[idx] = (n < N_NODES) ? g_agg[(size_t)n * DH + k] * sdi[r * 4 + (k >> 5)] : 0.f;
    }
    __syncthreads();
    int r = t >> 5, col = t & 31;
    float acc = 0.f;
#pragma unroll 8
    for (int k = 0; k < 128; k++) acc += sA[r * 128 + k] * sW[k * 32 + col];
    int n = n0 + r;
    if (n < N_NODES) {
        float v = acc + sb[col];
        out[(size_t)n * 32 + col] = 0.5f * v * (1.f + erff(v * 0.70710678118f));
    }
}

extern "C" void kernel_launch(void* const* d_in, const int* in_sizes, int n_in,
                              void* d_out, int out_size) {
    const float* NF = (const float*)d_in[0];   // node_features (N,128)
    const int*   EI = (const int*)  d_in[1];   // edge_index (E,2)
    const float* EF = (const float*)d_in[2];   // edge_features (E,32)
    const float* Wn = (const float*)d_in[3];   // W_node (128,128)
    const float* We = (const float*)d_in[4];   // W_edge (32,128)
    const float* AK = (const float*)d_in[5];   // attn_kernel (4,96)
    const float* Wo = (const float*)d_in[6];   // W_out (128,32)
    const float* bo = (const float*)d_in[7];   // b_out (32,)
    float* out = (float*)d_out;                // (N,32)

    k_prep_v<<<1, 128>>>(We, AK);
    k_zero<<<2048, 256>>>();
    k_node_gemm<<<(N_NODES + 63) / 64, 256>>>(NF, Wn, AK);
    k_edge<<<N_EDGES / 64, 256>>>(EI, EF);
    k_out<<<(N_NODES + 7) / 8, 256>>>(Wo, bo, out);
}